// round 4
// baseline (speedup 1.0000x reference)
#include <cuda_runtime.h>
#include <math.h>

#define BB 256
#define MAXLEN 31
#define TT 30
#define VV 10000
#define HH 512
#define EE 512
#define G4 2048   // 4*H
#define KX 512    // K dim of all GEMMs

// ---------------- scratch (static device globals; zero-initialized at load) ----
__device__ int   d_order[BB];
__device__ int   d_cnt[MAXLEN];                 // cnt[t] = #batches with dec_len > t
__device__ float d_hstate[BB * HH];             // never written: permanent zeros (h_{-1})
__device__ float d_cstate[2 * BB * HH];         // ping-pong c state
__device__ float d_Gpart[BB * G4];              // image part of gates + biases
__device__ float d_Z[(size_t)TT * BB * G4];     // x-part pre-gates, row r = t*256+b
__device__ float d_Hnew[(size_t)TT * BB * HH];  // h_new per step (input to projection)

// ---------------- PTX helpers -------------------------------------------------
__device__ __forceinline__ unsigned f2tf32(float x) {
    unsigned r;
    asm("cvt.rna.tf32.f32 %0, %1;" : "=r"(r) : "f"(x));
    return r;
}
__device__ __forceinline__ unsigned smem_u32(const void* p) {
    return (unsigned)__cvta_generic_to_shared(p);
}
#define LDM4(R0, R1, R2, R3, ADDR)                                            \
    asm volatile("ldmatrix.sync.aligned.m8n8.x4.shared.b16 {%0,%1,%2,%3},[%4];" \
                 : "=r"(R0), "=r"(R1), "=r"(R2), "=r"(R3) : "r"(ADDR))
#define MMA_TF32(C, A, B)                                                     \
    asm volatile("mma.sync.aligned.m16n8k8.row.col.f32.tf32.tf32.f32 "        \
                 "{%0,%1,%2,%3},{%4,%5,%6,%7},{%8,%9},{%0,%1,%2,%3};"         \
                 : "+f"((C)[0]), "+f"((C)[1]), "+f"((C)[2]), "+f"((C)[3])     \
                 : "r"((A)[0]), "r"((A)[1]), "r"((A)[2]), "r"((A)[3]),        \
                   "r"((B)[0]), "r"((B)[1]))

// ---------------- zero c-state each launch (graph replays must reset) ---------
__global__ void k_zero() {
    int i = blockIdx.x * 256 + threadIdx.x;
    d_cstate[i] = 0.f;
}

// ---------------- sort (stable descending), target + dec_len outputs, cnt[] ---
__global__ void k_sort(const int* __restrict__ caplen,
                       const int* __restrict__ w_input,
                       float* __restrict__ out, long long out_elems) {
    __shared__ int sl[BB];
    __shared__ int sdecl[BB];
    __shared__ int sord[BB];
    int tid = threadIdx.x;
    int len = caplen[tid];
    sl[tid] = len;
    __syncthreads();
    int rank = 0;
    for (int j = 0; j < BB; j++) {
        int lj = sl[j];
        rank += (lj > len) || (lj == len && j < tid);   // stable ties by index
    }
    sord[rank] = tid;
    sdecl[rank] = len - 1;
    d_order[rank] = tid;
    __syncthreads();

    const long long PRED = (long long)BB * MAXLEN * VV;
    if (out_elems >= PRED + BB * TT + BB)
        out[PRED + BB * TT + rank] = (float)(len - 1);
    if (out_elems >= PRED + BB * TT) {
        int src = sord[tid];
        for (int t = 0; t < TT; t++)
            out[PRED + (long long)tid * TT + t] = (float)w_input[src * MAXLEN + t + 1];
    }
    if (tid < MAXLEN) {
        int c = 0;
        for (int b = 0; b < BB; b++) c += (sdecl[b] > tid);
        d_cnt[tid] = c;
    }
}

// ---------------- SIMT GEMM tile: 64x64, KT=32, 256 thr, 4x4 micro ------------

// Gpart: C[b][j] = g_sorted[b] . W_ih[j][0:512] + b_ih[j] + b_hh[j]
__global__ __launch_bounds__(256) void k_gpart(const float* __restrict__ gimg,
                                               const float* __restrict__ W_ih,
                                               const float* __restrict__ b_ih,
                                               const float* __restrict__ b_hh) {
    __shared__ float As[32][68];
    __shared__ float Bs[32][68];
    __shared__ int rows[64];
    const int m0 = blockIdx.y * 64, n0 = blockIdx.x * 64;
    if (threadIdx.x < 64) rows[threadIdx.x] = d_order[m0 + threadIdx.x];
    __syncthreads();
    float acc[4][4] = {};
    const int tx = threadIdx.x & 15, ty = threadIdx.x >> 4;
    for (int k0 = 0; k0 < KX; k0 += 32) {
#pragma unroll
        for (int i = 0; i < 2; i++) {
            int vec = threadIdx.x * 2 + i;
            int m = vec >> 3, kv = (vec & 7) << 2;
            float4 va = *(const float4*)&gimg[(size_t)rows[m] * EE + k0 + kv];
            As[kv + 0][m] = va.x; As[kv + 1][m] = va.y; As[kv + 2][m] = va.z; As[kv + 3][m] = va.w;
            float4 vb = *(const float4*)&W_ih[(size_t)(n0 + m) * 1024 + k0 + kv];
            Bs[kv + 0][m] = vb.x; Bs[kv + 1][m] = vb.y; Bs[kv + 2][m] = vb.z; Bs[kv + 3][m] = vb.w;
        }
        __syncthreads();
#pragma unroll
        for (int kk = 0; kk < 32; kk++) {
            float4 a = *(const float4*)&As[kk][ty << 2];
            float4 b = *(const float4*)&Bs[kk][tx << 2];
            float av[4] = {a.x, a.y, a.z, a.w};
            float bv[4] = {b.x, b.y, b.z, b.w};
#pragma unroll
            for (int i2 = 0; i2 < 4; i2++)
#pragma unroll
                for (int j2 = 0; j2 < 4; j2++) acc[i2][j2] += av[i2] * bv[j2];
        }
        __syncthreads();
    }
#pragma unroll
    for (int i2 = 0; i2 < 4; i2++) {
        int m = m0 + (ty << 2) + i2;
#pragma unroll
        for (int j2 = 0; j2 < 4; j2++) {
            int n = n0 + (tx << 2) + j2;
            d_Gpart[m * G4 + n] = acc[i2][j2] + b_ih[n] + b_hh[n];
        }
    }
}

// Epart: Z[r][j] = emb[tok(r)] . W_ih[j][512:1024] + Gpart[b][j],  r = t*256+b
__global__ __launch_bounds__(256) void k_epart(const float* __restrict__ emb,
                                               const float* __restrict__ W_ih,
                                               const int* __restrict__ w_input) {
    const int m0 = blockIdx.y * 64, n0 = blockIdx.x * 64;
    const int t = m0 >> 8, b0 = m0 & 255;
    if (b0 >= d_cnt[t]) return;
    __shared__ float As[32][68];
    __shared__ float Bs[32][68];
    __shared__ int toks[64];
    if (threadIdx.x < 64)
        toks[threadIdx.x] = w_input[d_order[b0 + threadIdx.x] * MAXLEN + t];
    __syncthreads();
    float acc[4][4] = {};
    const int tx = threadIdx.x & 15, ty = threadIdx.x >> 4;
    for (int k0 = 0; k0 < KX; k0 += 32) {
#pragma unroll
        for (int i = 0; i < 2; i++) {
            int vec = threadIdx.x * 2 + i;
            int m = vec >> 3, kv = (vec & 7) << 2;
            float4 va = *(const float4*)&emb[(size_t)toks[m] * EE + k0 + kv];
            As[kv + 0][m] = va.x; As[kv + 1][m] = va.y; As[kv + 2][m] = va.z; As[kv + 3][m] = va.w;
            float4 vb = *(const float4*)&W_ih[(size_t)(n0 + m) * 1024 + 512 + k0 + kv];
            Bs[kv + 0][m] = vb.x; Bs[kv + 1][m] = vb.y; Bs[kv + 2][m] = vb.z; Bs[kv + 3][m] = vb.w;
        }
        __syncthreads();
#pragma unroll
        for (int kk = 0; kk < 32; kk++) {
            float4 a = *(const float4*)&As[kk][ty << 2];
            float4 b = *(const float4*)&Bs[kk][tx << 2];
            float av[4] = {a.x, a.y, a.z, a.w};
            float bv[4] = {b.x, b.y, b.z, b.w};
#pragma unroll
            for (int i2 = 0; i2 < 4; i2++)
#pragma unroll
                for (int j2 = 0; j2 < 4; j2++) acc[i2][j2] += av[i2] * bv[j2];
        }
        __syncthreads();
    }
#pragma unroll
    for (int i2 = 0; i2 < 4; i2++) {
        int lm = (ty << 2) + i2;
        int r = m0 + lm, b = b0 + lm;
#pragma unroll
        for (int j2 = 0; j2 < 4; j2++) {
            int n = n0 + (tx << 2) + j2;
            d_Z[(size_t)r * G4 + n] = acc[i2][j2] + d_Gpart[b * G4 + n];
        }
    }
}

// ---------------- fused recurrence step: gates GEMM (4 gates) + LSTM cell -----
// Block: 64 b-rows x 64 h-cols, all 4 gates. A = h_{t-1} (Hnew[t-1] or zeros).
__global__ __launch_bounds__(256) void k_stepcell(const float* __restrict__ W_hh, int t) {
    const int n0 = blockIdx.x * 64;   // h block
    const int m0 = blockIdx.y * 64;   // b block
    const int cnt = d_cnt[t];
    if (m0 >= cnt) return;
    __shared__ float As[32][68];
    __shared__ float Bs[4][32][68];
    const float* __restrict__ Aglob =
        (t == 0) ? d_hstate : (d_Hnew + (size_t)(t - 1) * BB * HH);
    float acc[4][4][4] = {};   // [gate][row][col]
    const int tx = threadIdx.x & 15, ty = threadIdx.x >> 4;
    for (int k0 = 0; k0 < KX; k0 += 32) {
#pragma unroll
        for (int i = 0; i < 2; i++) {
            int vec = threadIdx.x * 2 + i;
            int m = vec >> 3, kv = (vec & 7) << 2;
            float4 va = *(const float4*)&Aglob[(size_t)(m0 + m) * HH + k0 + kv];
            As[kv + 0][m] = va.x; As[kv + 1][m] = va.y; As[kv + 2][m] = va.z; As[kv + 3][m] = va.w;
        }
#pragma unroll
        for (int g = 0; g < 4; g++)
#pragma unroll
            for (int i = 0; i < 2; i++) {
                int vec = threadIdx.x * 2 + i;
                int m = vec >> 3, kv = (vec & 7) << 2;
                float4 vb = *(const float4*)&W_hh[(size_t)(g * 512 + n0 + m) * HH + k0 + kv];
                Bs[g][kv + 0][m] = vb.x; Bs[g][kv + 1][m] = vb.y;
                Bs[g][kv + 2][m] = vb.z; Bs[g][kv + 3][m] = vb.w;
            }
        __syncthreads();
#pragma unroll
        for (int kk = 0; kk < 32; kk++) {
            float4 a = *(const float4*)&As[kk][ty << 2];
            float av[4] = {a.x, a.y, a.z, a.w};
#pragma unroll
            for (int g = 0; g < 4; g++) {
                float4 b = *(const float4*)&Bs[g][kk][tx << 2];
                float bv[4] = {b.x, b.y, b.z, b.w};
#pragma unroll
                for (int i2 = 0; i2 < 4; i2++)
#pragma unroll
                    for (int j2 = 0; j2 < 4; j2++) acc[g][i2][j2] += av[i2] * bv[j2];
            }
        }
        __syncthreads();
    }
    const float* __restrict__ cr = d_cstate + (size_t)(t & 1) * BB * HH;
    float* __restrict__ cw = d_cstate + (size_t)((t + 1) & 1) * BB * HH;
#pragma unroll
    for (int i2 = 0; i2 < 4; i2++) {
        int b = m0 + (ty << 2) + i2;
        if (b >= cnt) continue;
        const float* Zr = d_Z + ((size_t)t * BB + b) * G4;
#pragma unroll
        for (int j2 = 0; j2 < 4; j2++) {
            int h = n0 + (tx << 2) + j2;
            float gi = acc[0][i2][j2] + Zr[h];
            float gf = acc[1][i2][j2] + Zr[512 + h];
            float gg = acc[2][i2][j2] + Zr[1024 + h];
            float go = acc[3][i2][j2] + Zr[1536 + h];
            float ii = 1.f / (1.f + expf(-gi));
            float ff = 1.f / (1.f + expf(-gf));
            float oo = 1.f / (1.f + expf(-go));
            float tg = tanhf(gg);
            float c = ff * cr[b * HH + h] + ii * tg;
            float hn = oo * tanhf(c);
            cw[b * HH + h] = c;
            d_Hnew[((size_t)t * BB + b) * HH + h] = hn;
        }
    }
}

// ---------------- projection: TF32 tensor-core GEMM ---------------------------
// out[(b*31+t)*V + n] = Hnew[t*256+b] . W_out[n] + b_out[n]
// Block tile 128x128, 8 warps (2m x 4n), warp tile 64x32, K staged 32.
__global__ __launch_bounds__(256) void k_proj(const float* __restrict__ W_out,
                                              const float* __restrict__ b_out,
                                              float* __restrict__ out) {
    __shared__ float As[128][36];
    __shared__ float Bs[128][36];
    const int t = blockIdx.y >> 1;
    const int b0 = (blockIdx.y & 1) * 128;
    if (b0 >= d_cnt[t]) return;
    const int m0g = t * 256 + b0;
    const int n0 = blockIdx.x * 128;
    const int tid = threadIdx.x;
    const int lane = tid & 31, wid = tid >> 5;
    const int wm = (wid >> 2) * 64, wn = (wid & 3) * 32;

    // ldmatrix lane addresses (pitch 36 floats; conflict-free phases)
    const int j = lane >> 3, r = lane & 7;
    unsigned aBase = smem_u32(&As[0][0]);
    unsigned bBase = smem_u32(&Bs[0][0]);
    unsigned aAddr[4], bAddr[2];
#pragma unroll
    for (int f = 0; f < 4; f++)
        aAddr[f] = aBase + ((wm + f * 16 + (j & 1) * 8 + r) * 36 + (j >> 1) * 4) * 4;
#pragma unroll
    for (int p = 0; p < 2; p++)
        bAddr[p] = bBase + ((wn + p * 16 + (j >> 1) * 8 + r) * 36 + (j & 1) * 4) * 4;

    float acc[4][4][4] = {};          // [m-frag][n-frag][c0..c3]
    const int lr = tid >> 3;          // load row base (0..31)
    const int lkq = tid & 7;          // k quad (0..7)

    for (int ks = 0; ks < 16; ks++) {
        const int k0 = ks * 32;
#pragma unroll
        for (int i = 0; i < 4; i++) {
            int mm = lr + i * 32;
            float4 va = *(const float4*)&d_Hnew[(size_t)(m0g + mm) * HH + k0 + lkq * 4];
            float4 vc;
            vc.x = __uint_as_float(f2tf32(va.x));
            vc.y = __uint_as_float(f2tf32(va.y));
            vc.z = __uint_as_float(f2tf32(va.z));
            vc.w = __uint_as_float(f2tf32(va.w));
            *(float4*)&As[mm][lkq * 4] = vc;
            int n = n0 + mm;
            float4 vb = make_float4(0.f, 0.f, 0.f, 0.f);
            if (n < VV) vb = *(const float4*)&W_out[(size_t)n * HH + k0 + lkq * 4];
            float4 vd;
            vd.x = __uint_as_float(f2tf32(vb.x));
            vd.y = __uint_as_float(f2tf32(vb.y));
            vd.z = __uint_as_float(f2tf32(vb.z));
            vd.w = __uint_as_float(f2tf32(vb.w));
            *(float4*)&Bs[mm][lkq * 4] = vd;
        }
        __syncthreads();
#pragma unroll
        for (int s = 0; s < 4; s++) {
            unsigned af[4][4];
            unsigned bf[4][2];
#pragma unroll
            for (int f = 0; f < 4; f++)
                LDM4(af[f][0], af[f][1], af[f][2], af[f][3], aAddr[f] + s * 32);
#pragma unroll
            for (int p = 0; p < 2; p++)
                LDM4(bf[2 * p][0], bf[2 * p][1], bf[2 * p + 1][0], bf[2 * p + 1][1],
                     bAddr[p] + s * 32);
#pragma unroll
            for (int mi = 0; mi < 4; mi++)
#pragma unroll
                for (int ni = 0; ni < 4; ni++)
                    MMA_TF32(acc[mi][ni], af[mi], bf[ni]);
        }
        __syncthreads();
    }

    // epilogue
    const int gr = lane >> 2, gc = (lane & 3) * 2;
#pragma unroll
    for (int mi = 0; mi < 4; mi++) {
        int lrow = wm + mi * 16 + gr;           // local row 0..127
        int b1 = b0 + lrow;                     // batch index (row of c0,c1)
        int b2 = b1 + 8;                        // row of c2,c3
#pragma unroll
        for (int ni = 0; ni < 4; ni++) {
            int n = n0 + wn + ni * 8 + gc;
            if (n < VV) {
                float bo0 = b_out[n], bo1 = b_out[n + 1];
                float2 v1 = make_float2(acc[mi][ni][0] + bo0, acc[mi][ni][1] + bo1);
                float2 v2 = make_float2(acc[mi][ni][2] + bo0, acc[mi][ni][3] + bo1);
                *(float2*)&out[((size_t)b1 * MAXLEN + t) * VV + n] = v1;
                *(float2*)&out[((size_t)b2 * MAXLEN + t) * VV + n] = v2;
            }
        }
    }
}

// log_softmax in place; inactive rows (t==30 or b>=cnt[t]) -> zeros
__global__ __launch_bounds__(256) void k_lsm(float* __restrict__ out) {
    __shared__ float sx[VV];
    __shared__ float red[256];
    int rid = blockIdx.x;
    int b = rid / MAXLEN, t = rid - b * MAXLEN;
    float* row = out + (size_t)rid * VV;
    int tid = threadIdx.x;
    bool active = (t < TT) && (b < d_cnt[t]);
    if (!active) {
        for (int i = tid; i < VV; i += 256) row[i] = 0.f;
        return;
    }
    float mx = -1e30f;
    for (int i = tid; i < VV; i += 256) {
        float v = row[i];
        sx[i] = v;
        mx = fmaxf(mx, v);
    }
    red[tid] = mx;
    __syncthreads();
    for (int s = 128; s > 0; s >>= 1) {
        if (tid < s) red[tid] = fmaxf(red[tid], red[tid + s]);
        __syncthreads();
    }
    mx = red[0];
    __syncthreads();
    float sm = 0.f;
    for (int i = tid; i < VV; i += 256) sm += expf(sx[i] - mx);
    red[tid] = sm;
    __syncthreads();
    for (int s = 128; s > 0; s >>= 1) {
        if (tid < s) red[tid] += red[tid + s];
        __syncthreads();
    }
    float lse = mx + logf(red[0]);
    for (int i = tid; i < VV; i += 256) row[i] = sx[i] - lse;
}

// ---------------- launch ------------------------------------------------------
extern "C" void kernel_launch(void* const* d_in, const int* in_sizes, int n_in,
                              void* d_out, int out_size) {
    const float* gimg    = (const float*)d_in[0];
    const int*   w_input = (const int*)  d_in[1];
    const int*   caplen  = (const int*)  d_in[2];
    const float* emb     = (const float*)d_in[3];
    const float* W_ih    = (const float*)d_in[4];
    const float* W_hh    = (const float*)d_in[5];
    const float* b_ih    = (const float*)d_in[6];
    const float* b_hh    = (const float*)d_in[7];
    const float* W_out   = (const float*)d_in[8];
    const float* b_out   = (const float*)d_in[9];
    float* out = (float*)d_out;

    k_zero<<<1024, 256>>>();
    k_sort<<<1, 256>>>(caplen, w_input, out, (long long)out_size);
    k_gpart<<<dim3(32, 4), 256>>>(gimg, W_ih, b_ih, b_hh);
    k_epart<<<dim3(32, 120), 256>>>(emb, W_ih, w_input);
    for (int t = 0; t < TT; t++) {
        k_stepcell<<<dim3(8, 4), 256>>>(W_hh, t);
    }
    k_proj<<<dim3(79, 60), 256>>>(W_out, b_out, out);
    k_lsm<<<BB * MAXLEN, 256>>>(out);
}

// round 5
// speedup vs baseline: 1.7469x; 1.7469x over previous
#include <cuda_runtime.h>
#include <math.h>

#define BB 256
#define MAXLEN 31
#define TT 30
#define VV 10000
#define HH 512
#define EE 512
#define G4 2048   // 4*H
#define KX 512    // K dim of all GEMMs

// ---------------- scratch (static device globals; zero-initialized at load) ----
__device__ int   d_order[BB];
__device__ int   d_cnt[MAXLEN];                 // cnt[t] = #batches with dec_len > t
__device__ int   d_tok[TT * BB];                // token at (t, sorted b)
__device__ float d_hstate[BB * HH];             // never written: permanent zeros (h_{-1})
__device__ float d_cstate[2 * BB * HH];         // ping-pong c state
__device__ float d_Gpart[BB * G4];              // image part of gates + biases
__device__ float d_Z[(size_t)TT * BB * G4];     // x-part pre-gates, row r = t*256+b
__device__ float d_Hnew[(size_t)TT * BB * HH];  // h_new per step (input to projection)

// ---------------- PTX helpers -------------------------------------------------
__device__ __forceinline__ unsigned f2tf32(float x) {
    unsigned r;
    asm("cvt.rna.tf32.f32 %0, %1;" : "=r"(r) : "f"(x));
    return r;
}
__device__ __forceinline__ float tf32f(float x) { return __uint_as_float(f2tf32(x)); }
__device__ __forceinline__ unsigned smem_u32(const void* p) {
    return (unsigned)__cvta_generic_to_shared(p);
}
#define LDM4(R0, R1, R2, R3, ADDR)                                            \
    asm volatile("ldmatrix.sync.aligned.m8n8.x4.shared.b16 {%0,%1,%2,%3},[%4];" \
                 : "=r"(R0), "=r"(R1), "=r"(R2), "=r"(R3) : "r"(ADDR))
#define MMA_TF32(C, A, B)                                                     \
    asm volatile("mma.sync.aligned.m16n8k8.row.col.f32.tf32.tf32.f32 "        \
                 "{%0,%1,%2,%3},{%4,%5,%6,%7},{%8,%9},{%0,%1,%2,%3};"         \
                 : "+f"((C)[0]), "+f"((C)[1]), "+f"((C)[2]), "+f"((C)[3])     \
                 : "r"((A)[0]), "r"((A)[1]), "r"((A)[2]), "r"((A)[3]),        \
                   "r"((B)[0]), "r"((B)[1]))

// ---------------- zero c-state each launch (graph replays must reset) ---------
__global__ void k_zero() {
    int i = blockIdx.x * 256 + threadIdx.x;
    d_cstate[i] = 0.f;
}

// ---------------- sort (stable descending), target + dec_len outputs, cnt[] ---
__global__ void k_sort(const int* __restrict__ caplen,
                       const int* __restrict__ w_input,
                       float* __restrict__ out, long long out_elems) {
    __shared__ int sl[BB];
    __shared__ int sdecl[BB];
    __shared__ int sord[BB];
    int tid = threadIdx.x;
    int len = caplen[tid];
    sl[tid] = len;
    __syncthreads();
    int rank = 0;
    for (int j = 0; j < BB; j++) {
        int lj = sl[j];
        rank += (lj > len) || (lj == len && j < tid);   // stable ties by index
    }
    sord[rank] = tid;
    sdecl[rank] = len - 1;
    d_order[rank] = tid;
    for (int t = 0; t < TT; t++)
        d_tok[t * BB + rank] = w_input[tid * MAXLEN + t];
    __syncthreads();

    const long long PRED = (long long)BB * MAXLEN * VV;
    if (out_elems >= PRED + BB * TT + BB)
        out[PRED + BB * TT + rank] = (float)(len - 1);
    if (out_elems >= PRED + BB * TT) {
        int src = sord[tid];
        for (int t = 0; t < TT; t++)
            out[PRED + (long long)tid * TT + t] = (float)w_input[src * MAXLEN + t + 1];
    }
    if (tid < MAXLEN) {
        int c = 0;
        for (int b = 0; b < BB; b++) c += (sdecl[b] > tid);
        d_cnt[tid] = c;
    }
}

// ---------------- Gpart (SIMT, small): C[b][j] = g.W_ih[:512]^T + biases ------
__global__ __launch_bounds__(256) void k_gpart(const float* __restrict__ gimg,
                                               const float* __restrict__ W_ih,
                                               const float* __restrict__ b_ih,
                                               const float* __restrict__ b_hh) {
    __shared__ float As[32][68];
    __shared__ float Bs[32][68];
    __shared__ int rows[64];
    const int m0 = blockIdx.y * 64, n0 = blockIdx.x * 64;
    if (threadIdx.x < 64) rows[threadIdx.x] = d_order[m0 + threadIdx.x];
    __syncthreads();
    float acc[4][4] = {};
    const int tx = threadIdx.x & 15, ty = threadIdx.x >> 4;
    for (int k0 = 0; k0 < KX; k0 += 32) {
#pragma unroll
        for (int i = 0; i < 2; i++) {
            int vec = threadIdx.x * 2 + i;
            int m = vec >> 3, kv = (vec & 7) << 2;
            float4 va = *(const float4*)&gimg[(size_t)rows[m] * EE + k0 + kv];
            As[kv + 0][m] = va.x; As[kv + 1][m] = va.y; As[kv + 2][m] = va.z; As[kv + 3][m] = va.w;
            float4 vb = *(const float4*)&W_ih[(size_t)(n0 + m) * 1024 + k0 + kv];
            Bs[kv + 0][m] = vb.x; Bs[kv + 1][m] = vb.y; Bs[kv + 2][m] = vb.z; Bs[kv + 3][m] = vb.w;
        }
        __syncthreads();
#pragma unroll
        for (int kk = 0; kk < 32; kk++) {
            float4 a = *(const float4*)&As[kk][ty << 2];
            float4 b = *(const float4*)&Bs[kk][tx << 2];
            float av[4] = {a.x, a.y, a.z, a.w};
            float bv[4] = {b.x, b.y, b.z, b.w};
#pragma unroll
            for (int i2 = 0; i2 < 4; i2++)
#pragma unroll
                for (int j2 = 0; j2 < 4; j2++) acc[i2][j2] += av[i2] * bv[j2];
        }
        __syncthreads();
    }
#pragma unroll
    for (int i2 = 0; i2 < 4; i2++) {
        int m = m0 + (ty << 2) + i2;
#pragma unroll
        for (int j2 = 0; j2 < 4; j2++) {
            int n = n0 + (tx << 2) + j2;
            d_Gpart[m * G4 + n] = acc[i2][j2] + b_ih[n] + b_hh[n];
        }
    }
}

// ---------------- Epart (TF32 MMA): Z[r][n] = emb[tok(r)].W_ih[n][512:] + Gpart
// Block 128x128, 8 warps (2m x 4n), warp tile 64x32. Grid (16, 60).
__global__ __launch_bounds__(256) void k_epart_tc(const float* __restrict__ emb,
                                                  const float* __restrict__ W_ih) {
    __shared__ float As[128][36];
    __shared__ float Bs[128][36];
    __shared__ int stok[128];
    const int t = blockIdx.y >> 1;
    const int b0 = (blockIdx.y & 1) * 128;
    if (b0 >= d_cnt[t]) return;
    const int r0 = t * 256 + b0;
    const int n0 = blockIdx.x * 128;
    const int tid = threadIdx.x;
    if (tid < 128) stok[tid] = d_tok[r0 + tid];
    __syncthreads();
    const int lane = tid & 31, wid = tid >> 5;
    const int wm = (wid >> 2) * 64, wn = (wid & 3) * 32;
    const int j = lane >> 3, r = lane & 7;
    unsigned aBase = smem_u32(&As[0][0]);
    unsigned bBase = smem_u32(&Bs[0][0]);
    unsigned aAddr[4], bAddr[2];
#pragma unroll
    for (int f = 0; f < 4; f++)
        aAddr[f] = aBase + ((wm + f * 16 + (j & 1) * 8 + r) * 36 + (j >> 1) * 4) * 4;
#pragma unroll
    for (int p = 0; p < 2; p++)
        bAddr[p] = bBase + ((wn + p * 16 + (j >> 1) * 8 + r) * 36 + (j & 1) * 4) * 4;

    float acc[4][4][4] = {};
    const int lr = tid >> 3;
    const int lkq = tid & 7;
    for (int ks = 0; ks < 16; ks++) {
        const int k0 = ks * 32;
#pragma unroll
        for (int i = 0; i < 4; i++) {
            int mm = lr + i * 32;
            float4 va = *(const float4*)&emb[(size_t)stok[mm] * EE + k0 + lkq * 4];
            float4 vc = make_float4(tf32f(va.x), tf32f(va.y), tf32f(va.z), tf32f(va.w));
            *(float4*)&As[mm][lkq * 4] = vc;
            float4 vb = *(const float4*)&W_ih[(size_t)(n0 + mm) * 1024 + 512 + k0 + lkq * 4];
            float4 vd = make_float4(tf32f(vb.x), tf32f(vb.y), tf32f(vb.z), tf32f(vb.w));
            *(float4*)&Bs[mm][lkq * 4] = vd;
        }
        __syncthreads();
#pragma unroll
        for (int s = 0; s < 4; s++) {
            unsigned af[4][4];
            unsigned bf[4][2];
#pragma unroll
            for (int f = 0; f < 4; f++)
                LDM4(af[f][0], af[f][1], af[f][2], af[f][3], aAddr[f] + s * 32);
#pragma unroll
            for (int p = 0; p < 2; p++)
                LDM4(bf[2 * p][0], bf[2 * p][1], bf[2 * p + 1][0], bf[2 * p + 1][1],
                     bAddr[p] + s * 32);
#pragma unroll
            for (int mi = 0; mi < 4; mi++)
#pragma unroll
                for (int ni = 0; ni < 4; ni++)
                    MMA_TF32(acc[mi][ni], af[mi], bf[ni]);
        }
        __syncthreads();
    }
    const int gr = lane >> 2, gc = (lane & 3) * 2;
#pragma unroll
    for (int mi = 0; mi < 4; mi++) {
        int lrow = wm + mi * 16 + gr;
        int b1 = b0 + lrow, b2 = b1 + 8;
        size_t z1 = ((size_t)t * BB + b1) * G4;
        size_t z2 = ((size_t)t * BB + b2) * G4;
#pragma unroll
        for (int ni = 0; ni < 4; ni++) {
            int n = n0 + wn + ni * 8 + gc;
            float g10 = d_Gpart[b1 * G4 + n], g11 = d_Gpart[b1 * G4 + n + 1];
            float g20 = d_Gpart[b2 * G4 + n], g21 = d_Gpart[b2 * G4 + n + 1];
            *(float2*)&d_Z[z1 + n] = make_float2(acc[mi][ni][0] + g10, acc[mi][ni][1] + g11);
            *(float2*)&d_Z[z2 + n] = make_float2(acc[mi][ni][2] + g20, acc[mi][ni][3] + g21);
        }
    }
}

// ---------------- fused recurrence (TF32 MMA + cell) --------------------------
// Block: 32 batch x 64 h x 4 gates == 32x256 GEMM. Grid (8 h-tiles, 8 m-tiles).
// Warp w: n-rows [w*32, w*32+32) == gate (q>>6), h (q&63) for q = n-row index.
__global__ __launch_bounds__(256) void k_stepcell_tc(const float* __restrict__ W_hh, int t) {
    const int cnt = d_cnt[t];
    const int m0 = blockIdx.y * 32;
    if (m0 >= cnt) return;
    const int n0g = blockIdx.x * 64;
    __shared__ float As[32][36];
    __shared__ float Bs[256][36];
    const float* __restrict__ Hprev =
        (t == 0) ? d_hstate : (d_Hnew + (size_t)(t - 1) * BB * HH);
    const int tid = threadIdx.x;
    const int lane = tid & 31, wid = tid >> 5;
    const int nb = wid * 32;
    const int j = lane >> 3, r = lane & 7;
    unsigned aBase = smem_u32(&As[0][0]);
    unsigned bBase = smem_u32(&Bs[0][0]);
    unsigned aAddr[2], bAddr[2];
#pragma unroll
    for (int f = 0; f < 2; f++)
        aAddr[f] = aBase + ((f * 16 + (j & 1) * 8 + r) * 36 + (j >> 1) * 4) * 4;
#pragma unroll
    for (int p = 0; p < 2; p++)
        bAddr[p] = bBase + ((nb + p * 16 + (j >> 1) * 8 + r) * 36 + (j & 1) * 4) * 4;

    float acc[2][4][4] = {};
    for (int ks = 0; ks < 16; ks++) {
        const int k0 = ks * 32;
        for (int idx = tid; idx < 2304; idx += 256) {
            int row = idx >> 3, kq = idx & 7;
            if (row < 32) {
                float4 v = *(const float4*)&Hprev[(size_t)(m0 + row) * HH + k0 + kq * 4];
                *(float4*)&As[row][kq * 4] =
                    make_float4(tf32f(v.x), tf32f(v.y), tf32f(v.z), tf32f(v.w));
            } else {
                int q = row - 32;
                int wr = (q >> 6) * 512 + n0g + (q & 63);
                float4 v = *(const float4*)&W_hh[(size_t)wr * HH + k0 + kq * 4];
                *(float4*)&Bs[q][kq * 4] =
                    make_float4(tf32f(v.x), tf32f(v.y), tf32f(v.z), tf32f(v.w));
            }
        }
        __syncthreads();
#pragma unroll
        for (int s = 0; s < 4; s++) {
            unsigned af[2][4];
            unsigned bf[4][2];
#pragma unroll
            for (int f = 0; f < 2; f++)
                LDM4(af[f][0], af[f][1], af[f][2], af[f][3], aAddr[f] + s * 32);
#pragma unroll
            for (int p = 0; p < 2; p++)
                LDM4(bf[2 * p][0], bf[2 * p][1], bf[2 * p + 1][0], bf[2 * p + 1][1],
                     bAddr[p] + s * 32);
#pragma unroll
            for (int mi = 0; mi < 2; mi++)
#pragma unroll
                for (int ni = 0; ni < 4; ni++)
                    MMA_TF32(acc[mi][ni], af[mi], bf[ni]);
        }
        __syncthreads();
    }

    // exchange gate slices through smem (reuse Bs region: 256*33 <= 256*36)
    float (*Cs)[33] = reinterpret_cast<float (*)[33]>(&Bs[0][0]);
    const int gr = lane >> 2, gc = (lane & 3) * 2;
#pragma unroll
    for (int mi = 0; mi < 2; mi++) {
        int r1 = mi * 16 + gr, r2 = r1 + 8;
#pragma unroll
        for (int ni = 0; ni < 4; ni++) {
            int q = nb + ni * 8 + gc;
            Cs[q][r1] = acc[mi][ni][0];
            Cs[q + 1][r1] = acc[mi][ni][1];
            Cs[q][r2] = acc[mi][ni][2];
            Cs[q + 1][r2] = acc[mi][ni][3];
        }
    }
    __syncthreads();

    const float* __restrict__ cr = d_cstate + (size_t)(t & 1) * BB * HH;
    float* __restrict__ cw = d_cstate + (size_t)((t + 1) & 1) * BB * HH;
#pragma unroll
    for (int e = 0; e < 8; e++) {
        int idx = tid + e * 256;          // 0..2047
        int hl = idx & 63, bl = idx >> 6; // coalesced over h
        int b = m0 + bl;
        if (b >= cnt) continue;
        int h = n0g + hl;
        const float* Zr = d_Z + ((size_t)t * BB + b) * G4;
        float gi = Cs[hl][bl] + Zr[h];
        float gf = Cs[64 + hl][bl] + Zr[512 + h];
        float gg = Cs[128 + hl][bl] + Zr[1024 + h];
        float go = Cs[192 + hl][bl] + Zr[1536 + h];
        float ii = 1.f / (1.f + expf(-gi));
        float ff = 1.f / (1.f + expf(-gf));
        float oo = 1.f / (1.f + expf(-go));
        float tg = tanhf(gg);
        float c = ff * cr[b * HH + h] + ii * tg;
        float hn = oo * tanhf(c);
        cw[b * HH + h] = c;
        d_Hnew[((size_t)t * BB + b) * HH + h] = hn;
    }
}

// ---------------- projection: TF32 tensor-core GEMM ---------------------------
__global__ __launch_bounds__(256) void k_proj(const float* __restrict__ W_out,
                                              const float* __restrict__ b_out,
                                              float* __restrict__ out) {
    __shared__ float As[128][36];
    __shared__ float Bs[128][36];
    const int t = blockIdx.y >> 1;
    const int b0 = (blockIdx.y & 1) * 128;
    if (b0 >= d_cnt[t]) return;
    const int m0g = t * 256 + b0;
    const int n0 = blockIdx.x * 128;
    const int tid = threadIdx.x;
    const int lane = tid & 31, wid = tid >> 5;
    const int wm = (wid >> 2) * 64, wn = (wid & 3) * 32;
    const int j = lane >> 3, r = lane & 7;
    unsigned aBase = smem_u32(&As[0][0]);
    unsigned bBase = smem_u32(&Bs[0][0]);
    unsigned aAddr[4], bAddr[2];
#pragma unroll
    for (int f = 0; f < 4; f++)
        aAddr[f] = aBase + ((wm + f * 16 + (j & 1) * 8 + r) * 36 + (j >> 1) * 4) * 4;
#pragma unroll
    for (int p = 0; p < 2; p++)
        bAddr[p] = bBase + ((wn + p * 16 + (j >> 1) * 8 + r) * 36 + (j & 1) * 4) * 4;

    float acc[4][4][4] = {};
    const int lr = tid >> 3;
    const int lkq = tid & 7;
    for (int ks = 0; ks < 16; ks++) {
        const int k0 = ks * 32;
#pragma unroll
        for (int i = 0; i < 4; i++) {
            int mm = lr + i * 32;
            float4 va = *(const float4*)&d_Hnew[(size_t)(m0g + mm) * HH + k0 + lkq * 4];
            *(float4*)&As[mm][lkq * 4] =
                make_float4(tf32f(va.x), tf32f(va.y), tf32f(va.z), tf32f(va.w));
            int n = n0 + mm;
            float4 vb = make_float4(0.f, 0.f, 0.f, 0.f);
            if (n < VV) vb = *(const float4*)&W_out[(size_t)n * HH + k0 + lkq * 4];
            *(float4*)&Bs[mm][lkq * 4] =
                make_float4(tf32f(vb.x), tf32f(vb.y), tf32f(vb.z), tf32f(vb.w));
        }
        __syncthreads();
#pragma unroll
        for (int s = 0; s < 4; s++) {
            unsigned af[4][4];
            unsigned bf[4][2];
#pragma unroll
            for (int f = 0; f < 4; f++)
                LDM4(af[f][0], af[f][1], af[f][2], af[f][3], aAddr[f] + s * 32);
#pragma unroll
            for (int p = 0; p < 2; p++)
                LDM4(bf[2 * p][0], bf[2 * p][1], bf[2 * p + 1][0], bf[2 * p + 1][1],
                     bAddr[p] + s * 32);
#pragma unroll
            for (int mi = 0; mi < 4; mi++)
#pragma unroll
                for (int ni = 0; ni < 4; ni++)
                    MMA_TF32(acc[mi][ni], af[mi], bf[ni]);
        }
        __syncthreads();
    }
    const int gr = lane >> 2, gc = (lane & 3) * 2;
#pragma unroll
    for (int mi = 0; mi < 4; mi++) {
        int lrow = wm + mi * 16 + gr;
        int b1 = b0 + lrow;
        int b2 = b1 + 8;
#pragma unroll
        for (int ni = 0; ni < 4; ni++) {
            int n = n0 + wn + ni * 8 + gc;
            if (n < VV) {
                float bo0 = b_out[n], bo1 = b_out[n + 1];
                float2 v1 = make_float2(acc[mi][ni][0] + bo0, acc[mi][ni][1] + bo1);
                float2 v2 = make_float2(acc[mi][ni][2] + bo0, acc[mi][ni][3] + bo1);
                *(float2*)&out[((size_t)b1 * MAXLEN + t) * VV + n] = v1;
                *(float2*)&out[((size_t)b2 * MAXLEN + t) * VV + n] = v2;
            }
        }
    }
}

// log_softmax in place; inactive rows (t==30 or b>=cnt[t]) -> zeros
__global__ __launch_bounds__(256) void k_lsm(float* __restrict__ out) {
    __shared__ float sx[VV];
    __shared__ float red[256];
    int rid = blockIdx.x;
    int b = rid / MAXLEN, t = rid - b * MAXLEN;
    float* row = out + (size_t)rid * VV;
    int tid = threadIdx.x;
    bool active = (t < TT) && (b < d_cnt[t]);
    if (!active) {
        for (int i = tid; i < VV; i += 256) row[i] = 0.f;
        return;
    }
    float mx = -1e30f;
    for (int i = tid; i < VV; i += 256) {
        float v = row[i];
        sx[i] = v;
        mx = fmaxf(mx, v);
    }
    red[tid] = mx;
    __syncthreads();
    for (int s = 128; s > 0; s >>= 1) {
        if (tid < s) red[tid] = fmaxf(red[tid], red[tid + s]);
        __syncthreads();
    }
    mx = red[0];
    __syncthreads();
    float sm = 0.f;
    for (int i = tid; i < VV; i += 256) sm += expf(sx[i] - mx);
    red[tid] = sm;
    __syncthreads();
    for (int s = 128; s > 0; s >>= 1) {
        if (tid < s) red[tid] += red[tid + s];
        __syncthreads();
    }
    float lse = mx + logf(red[0]);
    for (int i = tid; i < VV; i += 256) row[i] = sx[i] - lse;
}

// ---------------- launch ------------------------------------------------------
extern "C" void kernel_launch(void* const* d_in, const int* in_sizes, int n_in,
                              void* d_out, int out_size) {
    const float* gimg    = (const float*)d_in[0];
    const int*   w_input = (const int*)  d_in[1];
    const int*   caplen  = (const int*)  d_in[2];
    const float* emb     = (const float*)d_in[3];
    const float* W_ih    = (const float*)d_in[4];
    const float* W_hh    = (const float*)d_in[5];
    const float* b_ih    = (const float*)d_in[6];
    const float* b_hh    = (const float*)d_in[7];
    const float* W_out   = (const float*)d_in[8];
    const float* b_out   = (const float*)d_in[9];
    float* out = (float*)d_out;

    k_zero<<<1024, 256>>>();
    k_sort<<<1, 256>>>(caplen, w_input, out, (long long)out_size);
    k_gpart<<<dim3(32, 4), 256>>>(gimg, W_ih, b_ih, b_hh);
    k_epart_tc<<<dim3(16, 60), 256>>>(emb, W_ih);
    for (int t = 0; t < TT; t++) {
        k_stepcell_tc<<<dim3(8, 8), 256>>>(W_hh, t);
    }
    k_proj<<<dim3(79, 60), 256>>>(W_out, b_out, out);
    k_lsm<<<BB * MAXLEN, 256>>>(out);
}

// round 6
// speedup vs baseline: 1.8956x; 1.0851x over previous
#include <cuda_runtime.h>
#include <math.h>

#define BB 256
#define MAXLEN 31
#define TT 30
#define VV 10000
#define HH 512
#define EE 512
#define G4 2048   // 4*H
#define KX 512    // K dim of all GEMMs

// ---------------- scratch (static device globals; zero-initialized at load) ----
__device__ int   d_order[BB];
__device__ int   d_cnt[MAXLEN];                 // cnt[t] = #batches with dec_len > t
__device__ int   d_tok[TT * BB];                // token at (t, sorted b)
__device__ float d_hstate[BB * HH];             // never written: permanent zeros (h_{-1})
__device__ float d_cstate[2 * BB * HH];         // ping-pong c state
__device__ float d_Gpart[BB * G4];              // image part of gates + biases
__device__ float d_Z[(size_t)TT * BB * G4];     // x-part pre-gates, row r = t*256+b
__device__ float d_Hnew[(size_t)TT * BB * HH];  // h_new per step (input to projection)

// ---------------- PTX helpers -------------------------------------------------
__device__ __forceinline__ unsigned smem_u32(const void* p) {
    return (unsigned)__cvta_generic_to_shared(p);
}
#define LDM4(R0, R1, R2, R3, ADDR)                                            \
    asm volatile("ldmatrix.sync.aligned.m8n8.x4.shared.b16 {%0,%1,%2,%3},[%4];" \
                 : "=r"(R0), "=r"(R1), "=r"(R2), "=r"(R3) : "r"(ADDR))
#define MMA_TF32(C, A, B)                                                     \
    asm volatile("mma.sync.aligned.m16n8k8.row.col.f32.tf32.tf32.f32 "        \
                 "{%0,%1,%2,%3},{%4,%5,%6,%7},{%8,%9},{%0,%1,%2,%3};"         \
                 : "+f"((C)[0]), "+f"((C)[1]), "+f"((C)[2]), "+f"((C)[3])     \
                 : "r"((A)[0]), "r"((A)[1]), "r"((A)[2]), "r"((A)[3]),        \
                   "r"((B)[0]), "r"((B)[1]))
#define CPA16(DST, SRC)                                                       \
    asm volatile("cp.async.cg.shared.global [%0], [%1], 16;" ::               \
                 "r"(DST), "l"(SRC))
#define CPA16Z(DST, SRC, SZ)                                                  \
    asm volatile("cp.async.cg.shared.global [%0], [%1], 16, %2;" ::           \
                 "r"(DST), "l"(SRC), "r"(SZ))
#define CPA_COMMIT() asm volatile("cp.async.commit_group;")
#define CPA_WAIT1()  asm volatile("cp.async.wait_group 1;")
#define CPA_WAIT0()  asm volatile("cp.async.wait_group 0;")

// ---------------- zero c-state each launch (graph replays must reset) ---------
__global__ void k_zero() {
    int i = blockIdx.x * 256 + threadIdx.x;
    d_cstate[i] = 0.f;
}

// ---------------- sort (stable descending), target + dec_len outputs, cnt[] ---
__global__ void k_sort(const int* __restrict__ caplen,
                       const int* __restrict__ w_input,
                       float* __restrict__ out, long long out_elems) {
    __shared__ int sl[BB];
    __shared__ int sdecl[BB];
    __shared__ int sord[BB];
    int tid = threadIdx.x;
    int len = caplen[tid];
    sl[tid] = len;
    __syncthreads();
    int rank = 0;
    for (int j = 0; j < BB; j++) {
        int lj = sl[j];
        rank += (lj > len) || (lj == len && j < tid);
    }
    sord[rank] = tid;
    sdecl[rank] = len - 1;
    d_order[rank] = tid;
    for (int t = 0; t < TT; t++)
        d_tok[t * BB + rank] = w_input[tid * MAXLEN + t];
    __syncthreads();

    const long long PRED = (long long)BB * MAXLEN * VV;
    if (out_elems >= PRED + BB * TT + BB)
        out[PRED + BB * TT + rank] = (float)(len - 1);
    if (out_elems >= PRED + BB * TT) {
        int src = sord[tid];
        for (int t = 0; t < TT; t++)
            out[PRED + (long long)tid * TT + t] = (float)w_input[src * MAXLEN + t + 1];
    }
    if (tid < MAXLEN) {
        int c = 0;
        for (int b = 0; b < BB; b++) c += (sdecl[b] > tid);
        d_cnt[tid] = c;
    }
}

// ---------------- Gpart (SIMT, small): C[b][j] = g.W_ih[:512]^T + biases ------
__global__ __launch_bounds__(256) void k_gpart(const float* __restrict__ gimg,
                                               const float* __restrict__ W_ih,
                                               const float* __restrict__ b_ih,
                                               const float* __restrict__ b_hh) {
    __shared__ float As[32][68];
    __shared__ float Bs[32][68];
    __shared__ int rows[64];
    const int m0 = blockIdx.y * 64, n0 = blockIdx.x * 64;
    if (threadIdx.x < 64) rows[threadIdx.x] = d_order[m0 + threadIdx.x];
    __syncthreads();
    float acc[4][4] = {};
    const int tx = threadIdx.x & 15, ty = threadIdx.x >> 4;
    for (int k0 = 0; k0 < KX; k0 += 32) {
#pragma unroll
        for (int i = 0; i < 2; i++) {
            int vec = threadIdx.x * 2 + i;
            int m = vec >> 3, kv = (vec & 7) << 2;
            float4 va = *(const float4*)&gimg[(size_t)rows[m] * EE + k0 + kv];
            As[kv + 0][m] = va.x; As[kv + 1][m] = va.y; As[kv + 2][m] = va.z; As[kv + 3][m] = va.w;
            float4 vb = *(const float4*)&W_ih[(size_t)(n0 + m) * 1024 + k0 + kv];
            Bs[kv + 0][m] = vb.x; Bs[kv + 1][m] = vb.y; Bs[kv + 2][m] = vb.z; Bs[kv + 3][m] = vb.w;
        }
        __syncthreads();
#pragma unroll
        for (int kk = 0; kk < 32; kk++) {
            float4 a = *(const float4*)&As[kk][ty << 2];
            float4 b = *(const float4*)&Bs[kk][tx << 2];
            float av[4] = {a.x, a.y, a.z, a.w};
            float bv[4] = {b.x, b.y, b.z, b.w};
#pragma unroll
            for (int i2 = 0; i2 < 4; i2++)
#pragma unroll
                for (int j2 = 0; j2 < 4; j2++) acc[i2][j2] += av[i2] * bv[j2];
        }
        __syncthreads();
    }
#pragma unroll
    for (int i2 = 0; i2 < 4; i2++) {
        int m = m0 + (ty << 2) + i2;
#pragma unroll
        for (int j2 = 0; j2 < 4; j2++) {
            int n = n0 + (tx << 2) + j2;
            d_Gpart[m * G4 + n] = acc[i2][j2] + b_ih[n] + b_hh[n];
        }
    }
}

// ---------------- Epart (TF32 MMA + cp.async pipeline) ------------------------
// Z[r][n] = emb[tok(r)].W_ih[n][512:] + Gpart[b][n]. Block 128x128, BK=16, 2 stages.
// Grid (60 m-groups, 16 n-tiles).
__global__ __launch_bounds__(256) void k_epart_tc(const float* __restrict__ emb,
                                                  const float* __restrict__ W_ih) {
    __shared__ float As[2][128][20];
    __shared__ float Bs[2][128][20];
    __shared__ int stok[128];
    const int yo = blockIdx.x;
    const int t = yo >> 1;
    const int b0 = (yo & 1) * 128;
    if (b0 >= d_cnt[t]) return;
    const int r0 = t * 256 + b0;
    const int n0 = blockIdx.y * 128;
    const int tid = threadIdx.x;
    if (tid < 128) stok[tid] = d_tok[r0 + tid];
    __syncthreads();

    // per-thread load slots: rows lrow and lrow+64, k-quad lq
    const int lrow = tid >> 2, lq = tid & 3;
    const float* aS0 = &emb[(size_t)stok[lrow] * EE + lq * 4];
    const float* aS1 = &emb[(size_t)stok[lrow + 64] * EE + lq * 4];
    const float* bS0 = &W_ih[(size_t)(n0 + lrow) * 1024 + 512 + lq * 4];
    const float* bS1 = &W_ih[(size_t)(n0 + lrow + 64) * 1024 + 512 + lq * 4];
    unsigned dA0 = smem_u32(&As[0][lrow][lq * 4]);
    unsigned dA1 = smem_u32(&As[0][lrow + 64][lq * 4]);
    unsigned dB0 = smem_u32(&Bs[0][lrow][lq * 4]);
    unsigned dB1 = smem_u32(&Bs[0][lrow + 64][lq * 4]);
    const unsigned SSTR = 128 * 20 * 4;

    const int lane = tid & 31, wid = tid >> 5;
    const int wm = (wid >> 2) * 64, wn = (wid & 3) * 32;
    const int j = lane >> 3, r = lane & 7;
    unsigned aBase = smem_u32(&As[0][0][0]);
    unsigned bBase = smem_u32(&Bs[0][0][0]);
    unsigned aOff[4], bOff[2];
#pragma unroll
    for (int f = 0; f < 4; f++)
        aOff[f] = aBase + ((wm + f * 16 + (j & 1) * 8 + r) * 20 + (j >> 1) * 4) * 4;
#pragma unroll
    for (int p = 0; p < 2; p++)
        bOff[p] = bBase + ((wn + p * 16 + (j >> 1) * 8 + r) * 20 + (j & 1) * 4) * 4;

    float acc[4][4][4] = {};
    // prefetch stage 0
    CPA16(dA0, aS0); CPA16(dA1, aS1); CPA16(dB0, bS0); CPA16(dB1, bS1);
    CPA_COMMIT();
#pragma unroll 1
    for (int ks = 0; ks < 32; ks++) {
        int st = ks & 1;
        if (ks + 1 < 32) {
            int nst = (ks + 1) & 1;
            int k1 = (ks + 1) * 16;
            CPA16(dA0 + nst * SSTR, aS0 + k1);
            CPA16(dA1 + nst * SSTR, aS1 + k1);
            CPA16(dB0 + nst * SSTR, bS0 + k1);
            CPA16(dB1 + nst * SSTR, bS1 + k1);
            CPA_COMMIT();
            CPA_WAIT1();
        } else {
            CPA_WAIT0();
        }
        __syncthreads();
#pragma unroll
        for (int s = 0; s < 2; s++) {
            unsigned af[4][4], bf[4][2];
#pragma unroll
            for (int f = 0; f < 4; f++)
                LDM4(af[f][0], af[f][1], af[f][2], af[f][3], aOff[f] + st * SSTR + s * 32);
#pragma unroll
            for (int p = 0; p < 2; p++)
                LDM4(bf[2 * p][0], bf[2 * p][1], bf[2 * p + 1][0], bf[2 * p + 1][1],
                     bOff[p] + st * SSTR + s * 32);
#pragma unroll
            for (int mi = 0; mi < 4; mi++)
#pragma unroll
                for (int ni = 0; ni < 4; ni++)
                    MMA_TF32(acc[mi][ni], af[mi], bf[ni]);
        }
        __syncthreads();
    }
    const int gr = lane >> 2, gc = (lane & 3) * 2;
#pragma unroll
    for (int mi = 0; mi < 4; mi++) {
        int lrw = wm + mi * 16 + gr;
        int b1 = b0 + lrw, b2 = b1 + 8;
        size_t z1 = ((size_t)t * BB + b1) * G4;
        size_t z2 = ((size_t)t * BB + b2) * G4;
#pragma unroll
        for (int ni = 0; ni < 4; ni++) {
            int n = n0 + wn + ni * 8 + gc;
            float g10 = d_Gpart[b1 * G4 + n], g11 = d_Gpart[b1 * G4 + n + 1];
            float g20 = d_Gpart[b2 * G4 + n], g21 = d_Gpart[b2 * G4 + n + 1];
            *(float2*)&d_Z[z1 + n] = make_float2(acc[mi][ni][0] + g10, acc[mi][ni][1] + g11);
            *(float2*)&d_Z[z2 + n] = make_float2(acc[mi][ni][2] + g20, acc[mi][ni][3] + g21);
        }
    }
}

// ---------------- fused recurrence (TF32 MMA + cp.async + cell) ---------------
// Block: 32 batch x (4 gates x 64 h) == 32x256 GEMM, BK=16, 2 stages.
__global__ __launch_bounds__(256) void k_stepcell_tc(const float* __restrict__ W_hh, int t) {
    const int cnt = d_cnt[t];
    const int m0 = blockIdx.y * 32;
    if (m0 >= cnt) return;
    const int n0g = blockIdx.x * 64;
    __shared__ float As[2][32][20];
    __shared__ float Bs[2][256][20];
    const float* __restrict__ Hprev =
        (t == 0) ? d_hstate : (d_Hnew + (size_t)(t - 1) * BB * HH);
    const int tid = threadIdx.x;
    const int lane = tid & 31, wid = tid >> 5;
    const int nb = wid * 32;
    const int j = lane >> 3, r = lane & 7;
    unsigned aBase = smem_u32(&As[0][0][0]);
    unsigned bBase = smem_u32(&Bs[0][0][0]);
    const unsigned ASTR = 32 * 20 * 4, BSTR = 256 * 20 * 4;
    unsigned aOff[2], bOff[2];
#pragma unroll
    for (int f = 0; f < 2; f++)
        aOff[f] = aBase + ((f * 16 + (j & 1) * 8 + r) * 20 + (j >> 1) * 4) * 4;
#pragma unroll
    for (int p = 0; p < 2; p++)
        bOff[p] = bBase + ((nb + p * 16 + (j >> 1) * 8 + r) * 20 + (j & 1) * 4) * 4;

    // prefetch slots: 1152 float4 per stage (A:128, B:1024)
    float acc[2][4][4] = {};
#pragma unroll 1
    for (int ks = -1; ks < 32; ks++) {
        // issue prefetch for stage ks+1
        if (ks + 1 < 32) {
            int nst = (ks + 1) & 1;
            int k1 = (ks + 1) * 16;
            for (int idx = tid; idx < 1152; idx += 256) {
                if (idx < 128) {
                    int row = idx >> 2, q = idx & 3;
                    CPA16(smem_u32(&As[nst][row][q * 4]),
                          &Hprev[(size_t)(m0 + row) * HH + k1 + q * 4]);
                } else {
                    int bi = idx - 128;
                    int row = bi >> 2, q = bi & 3;
                    int wr = (row >> 6) * 512 + n0g + (row & 63);
                    CPA16(smem_u32(&Bs[nst][row][q * 4]),
                          &W_hh[(size_t)wr * HH + k1 + q * 4]);
                }
            }
            CPA_COMMIT();
        }
        if (ks < 0) continue;
        if (ks + 1 < 32) CPA_WAIT1(); else CPA_WAIT0();
        __syncthreads();
        int st = ks & 1;
#pragma unroll
        for (int s = 0; s < 2; s++) {
            unsigned af[2][4], bf[4][2];
#pragma unroll
            for (int f = 0; f < 2; f++)
                LDM4(af[f][0], af[f][1], af[f][2], af[f][3], aOff[f] + st * ASTR + s * 32);
#pragma unroll
            for (int p = 0; p < 2; p++)
                LDM4(bf[2 * p][0], bf[2 * p][1], bf[2 * p + 1][0], bf[2 * p + 1][1],
                     bOff[p] + st * BSTR + s * 32);
#pragma unroll
            for (int mi = 0; mi < 2; mi++)
#pragma unroll
                for (int ni = 0; ni < 4; ni++)
                    MMA_TF32(acc[mi][ni], af[mi], bf[ni]);
        }
        __syncthreads();
    }

    // exchange gate slices through smem (reuse Bs region: 256*33 <= 2*256*20)
    float (*Cs)[33] = reinterpret_cast<float (*)[33]>(&Bs[0][0][0]);
    const int gr = lane >> 2, gc = (lane & 3) * 2;
#pragma unroll
    for (int mi = 0; mi < 2; mi++) {
        int r1 = mi * 16 + gr, r2 = r1 + 8;
#pragma unroll
        for (int ni = 0; ni < 4; ni++) {
            int q = nb + ni * 8 + gc;
            Cs[q][r1] = acc[mi][ni][0];
            Cs[q + 1][r1] = acc[mi][ni][1];
            Cs[q][r2] = acc[mi][ni][2];
            Cs[q + 1][r2] = acc[mi][ni][3];
        }
    }
    __syncthreads();

    const float* __restrict__ cr = d_cstate + (size_t)(t & 1) * BB * HH;
    float* __restrict__ cw = d_cstate + (size_t)((t + 1) & 1) * BB * HH;
#pragma unroll
    for (int e = 0; e < 8; e++) {
        int idx = tid + e * 256;          // 0..2047
        int hl = idx & 63, bl = idx >> 6;
        int b = m0 + bl;
        if (b >= cnt) continue;
        int h = n0g + hl;
        const float* Zr = d_Z + ((size_t)t * BB + b) * G4;
        float gi = Cs[hl][bl] + Zr[h];
        float gf = Cs[64 + hl][bl] + Zr[512 + h];
        float gg = Cs[128 + hl][bl] + Zr[1024 + h];
        float go = Cs[192 + hl][bl] + Zr[1536 + h];
        float ii = 1.f / (1.f + expf(-gi));
        float ff = 1.f / (1.f + expf(-gf));
        float oo = 1.f / (1.f + expf(-go));
        float tg = tanhf(gg);
        float c = ff * cr[b * HH + h] + ii * tg;
        float hn = oo * tanhf(c);
        cw[b * HH + h] = c;
        d_Hnew[((size_t)t * BB + b) * HH + h] = hn;
    }
}

// ---------------- projection (TF32 MMA + cp.async pipeline) -------------------
// Block 128x128, BK=16, 2 stages. Grid (60 m-groups, 79 n-tiles).
__global__ __launch_bounds__(256) void k_proj(const float* __restrict__ W_out,
                                              const float* __restrict__ b_out,
                                              float* __restrict__ out) {
    __shared__ float As[2][128][20];
    __shared__ float Bs[2][128][20];
    const int yo = blockIdx.x;
    const int t = yo >> 1;
    const int b0 = (yo & 1) * 128;
    if (b0 >= d_cnt[t]) return;
    const int m0g = t * 256 + b0;
    const int n0 = blockIdx.y * 128;
    const int tid = threadIdx.x;

    const int lrow = tid >> 2, lq = tid & 3;
    const float* aS0 = &d_Hnew[(size_t)(m0g + lrow) * HH + lq * 4];
    const float* aS1 = &d_Hnew[(size_t)(m0g + lrow + 64) * HH + lq * 4];
    int nB0 = n0 + lrow, nB1 = n0 + lrow + 64;
    unsigned zB0 = nB0 < VV ? 16u : 0u, zB1 = nB1 < VV ? 16u : 0u;
    const float* bS0 = &W_out[(size_t)(nB0 < VV ? nB0 : VV - 1) * HH + lq * 4];
    const float* bS1 = &W_out[(size_t)(nB1 < VV ? nB1 : VV - 1) * HH + lq * 4];
    unsigned dA0 = smem_u32(&As[0][lrow][lq * 4]);
    unsigned dA1 = smem_u32(&As[0][lrow + 64][lq * 4]);
    unsigned dB0 = smem_u32(&Bs[0][lrow][lq * 4]);
    unsigned dB1 = smem_u32(&Bs[0][lrow + 64][lq * 4]);
    const unsigned SSTR = 128 * 20 * 4;

    const int lane = tid & 31, wid = tid >> 5;
    const int wm = (wid >> 2) * 64, wn = (wid & 3) * 32;
    const int j = lane >> 3, r = lane & 7;
    unsigned aBase = smem_u32(&As[0][0][0]);
    unsigned bBase = smem_u32(&Bs[0][0][0]);
    unsigned aOff[4], bOff[2];
#pragma unroll
    for (int f = 0; f < 4; f++)
        aOff[f] = aBase + ((wm + f * 16 + (j & 1) * 8 + r) * 20 + (j >> 1) * 4) * 4;
#pragma unroll
    for (int p = 0; p < 2; p++)
        bOff[p] = bBase + ((wn + p * 16 + (j >> 1) * 8 + r) * 20 + (j & 1) * 4) * 4;

    float acc[4][4][4] = {};
    CPA16(dA0, aS0); CPA16(dA1, aS1);
    CPA16Z(dB0, bS0, zB0); CPA16Z(dB1, bS1, zB1);
    CPA_COMMIT();
#pragma unroll 1
    for (int ks = 0; ks < 32; ks++) {
        int st = ks & 1;
        if (ks + 1 < 32) {
            int nst = (ks + 1) & 1;
            int k1 = (ks + 1) * 16;
            CPA16(dA0 + nst * SSTR, aS0 + k1);
            CPA16(dA1 + nst * SSTR, aS1 + k1);
            CPA16Z(dB0 + nst * SSTR, bS0 + k1, zB0);
            CPA16Z(dB1 + nst * SSTR, bS1 + k1, zB1);
            CPA_COMMIT();
            CPA_WAIT1();
        } else {
            CPA_WAIT0();
        }
        __syncthreads();
#pragma unroll
        for (int s = 0; s < 2; s++) {
            unsigned af[4][4], bf[4][2];
#pragma unroll
            for (int f = 0; f < 4; f++)
                LDM4(af[f][0], af[f][1], af[f][2], af[f][3], aOff[f] + st * SSTR + s * 32);
#pragma unroll
            for (int p = 0; p < 2; p++)
                LDM4(bf[2 * p][0], bf[2 * p][1], bf[2 * p + 1][0], bf[2 * p + 1][1],
                     bOff[p] + st * SSTR + s * 32);
#pragma unroll
            for (int mi = 0; mi < 4; mi++)
#pragma unroll
                for (int ni = 0; ni < 4; ni++)
                    MMA_TF32(acc[mi][ni], af[mi], bf[ni]);
        }
        __syncthreads();
    }
    const int gr = lane >> 2, gc = (lane & 3) * 2;
#pragma unroll
    for (int mi = 0; mi < 4; mi++) {
        int lrw = wm + mi * 16 + gr;
        int b1 = b0 + lrw;
        int b2 = b1 + 8;
#pragma unroll
        for (int ni = 0; ni < 4; ni++) {
            int n = n0 + wn + ni * 8 + gc;
            if (n < VV) {
                float bo0 = b_out[n], bo1 = b_out[n + 1];
                float2 v1 = make_float2(acc[mi][ni][0] + bo0, acc[mi][ni][1] + bo1);
                float2 v2 = make_float2(acc[mi][ni][2] + bo0, acc[mi][ni][3] + bo1);
                *(float2*)&out[((size_t)b1 * MAXLEN + t) * VV + n] = v1;
                *(float2*)&out[((size_t)b2 * MAXLEN + t) * VV + n] = v2;
            }
        }
    }
}

// log_softmax in place; inactive rows (t==30 or b>=cnt[t]) -> zeros
__global__ __launch_bounds__(256) void k_lsm(float* __restrict__ out) {
    __shared__ float sx[VV];
    __shared__ float red[256];
    int rid = blockIdx.x;
    int b = rid / MAXLEN, t = rid - b * MAXLEN;
    float* row = out + (size_t)rid * VV;
    int tid = threadIdx.x;
    bool active = (t < TT) && (b < d_cnt[t]);
    if (!active) {
        for (int i = tid; i < VV; i += 256) row[i] = 0.f;
        return;
    }
    float mx = -1e30f;
    for (int i = tid; i < VV; i += 256) {
        float v = row[i];
        sx[i] = v;
        mx = fmaxf(mx, v);
    }
    red[tid] = mx;
    __syncthreads();
    for (int s = 128; s > 0; s >>= 1) {
        if (tid < s) red[tid] = fmaxf(red[tid], red[tid + s]);
        __syncthreads();
    }
    mx = red[0];
    __syncthreads();
    float sm = 0.f;
    for (int i = tid; i < VV; i += 256) sm += expf(sx[i] - mx);
    red[tid] = sm;
    __syncthreads();
    for (int s = 128; s > 0; s >>= 1) {
        if (tid < s) red[tid] += red[tid + s];
        __syncthreads();
    }
    float lse = mx + logf(red[0]);
    for (int i = tid; i < VV; i += 256) row[i] = sx[i] - lse;
}

// ---------------- launch ------------------------------------------------------
extern "C" void kernel_launch(void* const* d_in, const int* in_sizes, int n_in,
                              void* d_out, int out_size) {
    const float* gimg    = (const float*)d_in[0];
    const int*   w_input = (const int*)  d_in[1];
    const int*   caplen  = (const int*)  d_in[2];
    const float* emb     = (const float*)d_in[3];
    const float* W_ih    = (const float*)d_in[4];
    const float* W_hh    = (const float*)d_in[5];
    const float* b_ih    = (const float*)d_in[6];
    const float* b_hh    = (const float*)d_in[7];
    const float* W_out   = (const float*)d_in[8];
    const float* b_out   = (const float*)d_in[9];
    float* out = (float*)d_out;

    k_zero<<<1024, 256>>>();
    k_sort<<<1, 256>>>(caplen, w_input, out, (long long)out_size);
    k_gpart<<<dim3(32, 4), 256>>>(gimg, W_ih, b_ih, b_hh);
    k_epart_tc<<<dim3(60, 16), 256>>>(emb, W_ih);
    for (int t = 0; t < TT; t++) {
        k_stepcell_tc<<<dim3(8, 8), 256>>>(W_hh, t);
    }
    k_proj<<<dim3(60, 79), 256>>>(W_out, b_out, out);
    k_lsm<<<BB * MAXLEN, 256>>>(out);
}

// round 8
// speedup vs baseline: 2.1638x; 1.1415x over previous
#include <cuda_runtime.h>
#include <cuda_bf16.h>
#include <math.h>

#define BB 256
#define MAXLEN 31
#define TT 30
#define VV 10000
#define HH 512
#define EE 512
#define G4 2048   // 4*H
#define KX 512    // K dim of all GEMMs

// ---------------- scratch (static device globals; zero-initialized at load) ----
__device__ int   d_order[BB];
__device__ int   d_cnt[MAXLEN];                 // cnt[t] = #batches with dec_len > t
__device__ int   d_tok[TT * BB];                // token at (t, sorted b)
__device__ float d_hstate[BB * HH];             // never written: permanent zeros (h_{-1})
__device__ float d_cstate[2 * BB * HH];         // ping-pong c state
__device__ float d_Gpart[BB * G4];              // image part of gates + biases
__device__ float d_Z[(size_t)TT * BB * G4];     // x-part pre-gates, row r = t*256+b
__device__ float d_Hnew[(size_t)TT * BB * HH];  // h_new per step (tf32 path)
__device__ __nv_bfloat16 d_Hnew_bf[(size_t)TT * BB * HH];  // bf16 mirror for proj
__device__ __nv_bfloat16 d_Wout_bf[(size_t)VV * HH];       // bf16 W_out

// ---------------- PTX helpers -------------------------------------------------
__device__ __forceinline__ unsigned smem_u32(const void* p) {
    return (unsigned)__cvta_generic_to_shared(p);
}
#define LDM4(R0, R1, R2, R3, ADDR)                                            \
    asm volatile("ldmatrix.sync.aligned.m8n8.x4.shared.b16 {%0,%1,%2,%3},[%4];" \
                 : "=r"(R0), "=r"(R1), "=r"(R2), "=r"(R3) : "r"(ADDR))
#define MMA_TF32(C, A, B)                                                     \
    asm volatile("mma.sync.aligned.m16n8k8.row.col.f32.tf32.tf32.f32 "        \
                 "{%0,%1,%2,%3},{%4,%5,%6,%7},{%8,%9},{%0,%1,%2,%3};"         \
                 : "+f"((C)[0]), "+f"((C)[1]), "+f"((C)[2]), "+f"((C)[3])     \
                 : "r"((A)[0]), "r"((A)[1]), "r"((A)[2]), "r"((A)[3]),        \
                   "r"((B)[0]), "r"((B)[1]))
#define MMA_BF16(C, A, B)                                                     \
    asm volatile("mma.sync.aligned.m16n8k16.row.col.f32.bf16.bf16.f32 "       \
                 "{%0,%1,%2,%3},{%4,%5,%6,%7},{%8,%9},{%0,%1,%2,%3};"         \
                 : "+f"((C)[0]), "+f"((C)[1]), "+f"((C)[2]), "+f"((C)[3])     \
                 : "r"((A)[0]), "r"((A)[1]), "r"((A)[2]), "r"((A)[3]),        \
                   "r"((B)[0]), "r"((B)[1]))
#define CPA16(DST, SRC)                                                       \
    asm volatile("cp.async.cg.shared.global [%0], [%1], 16;" ::               \
                 "r"(DST), "l"(SRC))
#define CPA16Z(DST, SRC, SZ)                                                  \
    asm volatile("cp.async.cg.shared.global [%0], [%1], 16, %2;" ::           \
                 "r"(DST), "l"(SRC), "r"(SZ))
#define CPA_COMMIT() asm volatile("cp.async.commit_group;")
#define CPA_WAIT1()  asm volatile("cp.async.wait_group 1;")
#define CPA_WAIT0()  asm volatile("cp.async.wait_group 0;")

// ---------------- zero c-state each launch (graph replays must reset) ---------
__global__ void k_zero() {
    int i = blockIdx.x * 256 + threadIdx.x;
    d_cstate[i] = 0.f;
}

// ---------------- W_out -> bf16 (once per launch) -----------------------------
__global__ __launch_bounds__(256) void k_conv_wout(const float* __restrict__ W_out) {
    int i = blockIdx.x * 256 + threadIdx.x;      // 1.28M threads, 4 elems each
    float4 v = *(const float4*)&W_out[(size_t)i * 4];
    __nv_bfloat162 p0 = {__float2bfloat16(v.x), __float2bfloat16(v.y)};
    __nv_bfloat162 p1 = {__float2bfloat16(v.z), __float2bfloat16(v.w)};
    *(__nv_bfloat162*)&d_Wout_bf[(size_t)i * 4] = p0;
    *(__nv_bfloat162*)&d_Wout_bf[(size_t)i * 4 + 2] = p1;
}

// ---------------- sort (stable descending), target + dec_len outputs, cnt[] ---
__global__ void k_sort(const int* __restrict__ caplen,
                       const int* __restrict__ w_input,
                       float* __restrict__ out, long long out_elems) {
    __shared__ int sl[BB];
    __shared__ int sdecl[BB];
    __shared__ int sord[BB];
    int tid = threadIdx.x;
    int len = caplen[tid];
    sl[tid] = len;
    __syncthreads();
    int rank = 0;
    for (int j = 0; j < BB; j++) {
        int lj = sl[j];
        rank += (lj > len) || (lj == len && j < tid);
    }
    sord[rank] = tid;
    sdecl[rank] = len - 1;
    d_order[rank] = tid;
    for (int t = 0; t < TT; t++)
        d_tok[t * BB + rank] = w_input[tid * MAXLEN + t];
    __syncthreads();

    const long long PRED = (long long)BB * MAXLEN * VV;
    if (out_elems >= PRED + BB * TT + BB)
        out[PRED + BB * TT + rank] = (float)(len - 1);
    if (out_elems >= PRED + BB * TT) {
        int src = sord[tid];
        for (int t = 0; t < TT; t++)
            out[PRED + (long long)tid * TT + t] = (float)w_input[src * MAXLEN + t + 1];
    }
    if (tid < MAXLEN) {
        int c = 0;
        for (int b = 0; b < BB; b++) c += (sdecl[b] > tid);
        d_cnt[tid] = c;
    }
}

// ---------------- Gpart (SIMT, small): C[b][j] = g.W_ih[:512]^T + biases ------
__global__ __launch_bounds__(256) void k_gpart(const float* __restrict__ gimg,
                                               const float* __restrict__ W_ih,
                                               const float* __restrict__ b_ih,
                                               const float* __restrict__ b_hh) {
    __shared__ float As[32][68];
    __shared__ float Bs[32][68];
    __shared__ int rows[64];
    const int m0 = blockIdx.y * 64, n0 = blockIdx.x * 64;
    if (threadIdx.x < 64) rows[threadIdx.x] = d_order[m0 + threadIdx.x];
    __syncthreads();
    float acc[4][4] = {};
    const int tx = threadIdx.x & 15, ty = threadIdx.x >> 4;
    for (int k0 = 0; k0 < KX; k0 += 32) {
#pragma unroll
        for (int i = 0; i < 2; i++) {
            int vec = threadIdx.x * 2 + i;
            int m = vec >> 3, kv = (vec & 7) << 2;
            float4 va = *(const float4*)&gimg[(size_t)rows[m] * EE + k0 + kv];
            As[kv + 0][m] = va.x; As[kv + 1][m] = va.y; As[kv + 2][m] = va.z; As[kv + 3][m] = va.w;
            float4 vb = *(const float4*)&W_ih[(size_t)(n0 + m) * 1024 + k0 + kv];
            Bs[kv + 0][m] = vb.x; Bs[kv + 1][m] = vb.y; Bs[kv + 2][m] = vb.z; Bs[kv + 3][m] = vb.w;
        }
        __syncthreads();
#pragma unroll
        for (int kk = 0; kk < 32; kk++) {
            float4 a = *(const float4*)&As[kk][ty << 2];
            float4 b = *(const float4*)&Bs[kk][tx << 2];
            float av[4] = {a.x, a.y, a.z, a.w};
            float bv[4] = {b.x, b.y, b.z, b.w};
#pragma unroll
            for (int i2 = 0; i2 < 4; i2++)
#pragma unroll
                for (int j2 = 0; j2 < 4; j2++) acc[i2][j2] += av[i2] * bv[j2];
        }
        __syncthreads();
    }
#pragma unroll
    for (int i2 = 0; i2 < 4; i2++) {
        int m = m0 + (ty << 2) + i2;
#pragma unroll
        for (int j2 = 0; j2 < 4; j2++) {
            int n = n0 + (tx << 2) + j2;
            d_Gpart[m * G4 + n] = acc[i2][j2] + b_ih[n] + b_hh[n];
        }
    }
}

// ---------------- Epart (TF32 MMA + cp.async pipeline) ------------------------
__global__ __launch_bounds__(256) void k_epart_tc(const float* __restrict__ emb,
                                                  const float* __restrict__ W_ih) {
    __shared__ float As[2][128][20];
    __shared__ float Bs[2][128][20];
    __shared__ int stok[128];
    const int yo = blockIdx.x;
    const int t = yo >> 1;
    const int b0 = (yo & 1) * 128;
    if (b0 >= d_cnt[t]) return;
    const int r0 = t * 256 + b0;
    const int n0 = blockIdx.y * 128;
    const int tid = threadIdx.x;
    if (tid < 128) stok[tid] = d_tok[r0 + tid];
    __syncthreads();

    const int lrow = tid >> 2, lq = tid & 3;
    const float* aS0 = &emb[(size_t)stok[lrow] * EE + lq * 4];
    const float* aS1 = &emb[(size_t)stok[lrow + 64] * EE + lq * 4];
    const float* bS0 = &W_ih[(size_t)(n0 + lrow) * 1024 + 512 + lq * 4];
    const float* bS1 = &W_ih[(size_t)(n0 + lrow + 64) * 1024 + 512 + lq * 4];
    unsigned dA0 = smem_u32(&As[0][lrow][lq * 4]);
    unsigned dA1 = smem_u32(&As[0][lrow + 64][lq * 4]);
    unsigned dB0 = smem_u32(&Bs[0][lrow][lq * 4]);
    unsigned dB1 = smem_u32(&Bs[0][lrow + 64][lq * 4]);
    const unsigned SSTR = 128 * 20 * 4;

    const int lane = tid & 31, wid = tid >> 5;
    const int wm = (wid >> 2) * 64, wn = (wid & 3) * 32;
    const int j = lane >> 3, r = lane & 7;
    unsigned aBase = smem_u32(&As[0][0][0]);
    unsigned bBase = smem_u32(&Bs[0][0][0]);
    unsigned aOff[4], bOff[2];
#pragma unroll
    for (int f = 0; f < 4; f++)
        aOff[f] = aBase + ((wm + f * 16 + (j & 1) * 8 + r) * 20 + (j >> 1) * 4) * 4;
#pragma unroll
    for (int p = 0; p < 2; p++)
        bOff[p] = bBase + ((wn + p * 16 + (j >> 1) * 8 + r) * 20 + (j & 1) * 4) * 4;

    float acc[4][4][4] = {};
    CPA16(dA0, aS0); CPA16(dA1, aS1); CPA16(dB0, bS0); CPA16(dB1, bS1);
    CPA_COMMIT();
#pragma unroll 1
    for (int ks = 0; ks < 32; ks++) {
        int st = ks & 1;
        if (ks + 1 < 32) {
            int nst = (ks + 1) & 1;
            int k1 = (ks + 1) * 16;
            CPA16(dA0 + nst * SSTR, aS0 + k1);
            CPA16(dA1 + nst * SSTR, aS1 + k1);
            CPA16(dB0 + nst * SSTR, bS0 + k1);
            CPA16(dB1 + nst * SSTR, bS1 + k1);
            CPA_COMMIT();
            CPA_WAIT1();
        } else {
            CPA_WAIT0();
        }
        __syncthreads();
#pragma unroll
        for (int s = 0; s < 2; s++) {
            unsigned af[4][4], bf[4][2];
#pragma unroll
            for (int f = 0; f < 4; f++)
                LDM4(af[f][0], af[f][1], af[f][2], af[f][3], aOff[f] + st * SSTR + s * 32);
#pragma unroll
            for (int p = 0; p < 2; p++)
                LDM4(bf[2 * p][0], bf[2 * p][1], bf[2 * p + 1][0], bf[2 * p + 1][1],
                     bOff[p] + st * SSTR + s * 32);
#pragma unroll
            for (int mi = 0; mi < 4; mi++)
#pragma unroll
                for (int ni = 0; ni < 4; ni++)
                    MMA_TF32(acc[mi][ni], af[mi], bf[ni]);
        }
        __syncthreads();
    }
    const int gr = lane >> 2, gc = (lane & 3) * 2;
#pragma unroll
    for (int mi = 0; mi < 4; mi++) {
        int lrw = wm + mi * 16 + gr;
        int b1 = b0 + lrw, b2 = b1 + 8;
        size_t z1 = ((size_t)t * BB + b1) * G4;
        size_t z2 = ((size_t)t * BB + b2) * G4;
#pragma unroll
        for (int ni = 0; ni < 4; ni++) {
            int n = n0 + wn + ni * 8 + gc;
            float g10 = d_Gpart[b1 * G4 + n], g11 = d_Gpart[b1 * G4 + n + 1];
            float g20 = d_Gpart[b2 * G4 + n], g21 = d_Gpart[b2 * G4 + n + 1];
            *(float2*)&d_Z[z1 + n] = make_float2(acc[mi][ni][0] + g10, acc[mi][ni][1] + g11);
            *(float2*)&d_Z[z2 + n] = make_float2(acc[mi][ni][2] + g20, acc[mi][ni][3] + g21);
        }
    }
}

// ---------------- fused recurrence (TF32 MMA + cp.async + cell) ---------------
__global__ __launch_bounds__(256) void k_stepcell_tc(const float* __restrict__ W_hh, int t) {
    const int cnt = d_cnt[t];
    const int m0 = blockIdx.y * 32;
    if (m0 >= cnt) return;
    const int n0g = blockIdx.x * 64;
    __shared__ float As[2][32][20];
    __shared__ float Bs[2][256][20];
    const float* __restrict__ Hprev =
        (t == 0) ? d_hstate : (d_Hnew + (size_t)(t - 1) * BB * HH);
    const int tid = threadIdx.x;
    const int lane = tid & 31, wid = tid >> 5;
    const int nb = wid * 32;
    const int j = lane >> 3, r = lane & 7;
    unsigned aBase = smem_u32(&As[0][0][0]);
    unsigned bBase = smem_u32(&Bs[0][0][0]);
    const unsigned ASTR = 32 * 20 * 4, BSTR = 256 * 20 * 4;
    unsigned aOff[2], bOff[2];
#pragma unroll
    for (int f = 0; f < 2; f++)
        aOff[f] = aBase + ((f * 16 + (j & 1) * 8 + r) * 20 + (j >> 1) * 4) * 4;
#pragma unroll
    for (int p = 0; p < 2; p++)
        bOff[p] = bBase + ((nb + p * 16 + (j >> 1) * 8 + r) * 20 + (j & 1) * 4) * 4;

    float acc[2][4][4] = {};
#pragma unroll 1
    for (int ks = -1; ks < 32; ks++) {
        if (ks + 1 < 32) {
            int nst = (ks + 1) & 1;
            int k1 = (ks + 1) * 16;
            for (int idx = tid; idx < 1152; idx += 256) {
                if (idx < 128) {
                    int row = idx >> 2, q = idx & 3;
                    CPA16(smem_u32(&As[nst][row][q * 4]),
                          &Hprev[(size_t)(m0 + row) * HH + k1 + q * 4]);
                } else {
                    int bi = idx - 128;
                    int row = bi >> 2, q = bi & 3;
                    int wr = (row >> 6) * 512 + n0g + (row & 63);
                    CPA16(smem_u32(&Bs[nst][row][q * 4]),
                          &W_hh[(size_t)wr * HH + k1 + q * 4]);
                }
            }
            CPA_COMMIT();
        }
        if (ks < 0) continue;
        if (ks + 1 < 32) CPA_WAIT1(); else CPA_WAIT0();
        __syncthreads();
        int st = ks & 1;
#pragma unroll
        for (int s = 0; s < 2; s++) {
            unsigned af[2][4], bf[4][2];
#pragma unroll
            for (int f = 0; f < 2; f++)
                LDM4(af[f][0], af[f][1], af[f][2], af[f][3], aOff[f] + st * ASTR + s * 32);
#pragma unroll
            for (int p = 0; p < 2; p++)
                LDM4(bf[2 * p][0], bf[2 * p][1], bf[2 * p + 1][0], bf[2 * p + 1][1],
                     bOff[p] + st * BSTR + s * 32);
#pragma unroll
            for (int mi = 0; mi < 2; mi++)
#pragma unroll
                for (int ni = 0; ni < 4; ni++)
                    MMA_TF32(acc[mi][ni], af[mi], bf[ni]);
        }
        __syncthreads();
    }

    float (*Cs)[33] = reinterpret_cast<float (*)[33]>(&Bs[0][0][0]);
    const int gr = lane >> 2, gc = (lane & 3) * 2;
#pragma unroll
    for (int mi = 0; mi < 2; mi++) {
        int r1 = mi * 16 + gr, r2 = r1 + 8;
#pragma unroll
        for (int ni = 0; ni < 4; ni++) {
            int q = nb + ni * 8 + gc;
            Cs[q][r1] = acc[mi][ni][0];
            Cs[q + 1][r1] = acc[mi][ni][1];
            Cs[q][r2] = acc[mi][ni][2];
            Cs[q + 1][r2] = acc[mi][ni][3];
        }
    }
    __syncthreads();

    const float* __restrict__ cr = d_cstate + (size_t)(t & 1) * BB * HH;
    float* __restrict__ cw = d_cstate + (size_t)((t + 1) & 1) * BB * HH;
#pragma unroll
    for (int e = 0; e < 8; e++) {
        int idx = tid + e * 256;
        int hl = idx & 63, bl = idx >> 6;
        int b = m0 + bl;
        if (b >= cnt) continue;
        int h = n0g + hl;
        const float* Zr = d_Z + ((size_t)t * BB + b) * G4;
        float gi = Cs[hl][bl] + Zr[h];
        float gf = Cs[64 + hl][bl] + Zr[512 + h];
        float gg = Cs[128 + hl][bl] + Zr[1024 + h];
        float go = Cs[192 + hl][bl] + Zr[1536 + h];
        float ii = 1.f / (1.f + expf(-gi));
        float ff = 1.f / (1.f + expf(-gf));
        float oo = 1.f / (1.f + expf(-go));
        float tg = tanhf(gg);
        float c = ff * cr[b * HH + h] + ii * tg;
        float hn = oo * tanhf(c);
        cw[b * HH + h] = c;
        size_t hidx = ((size_t)t * BB + b) * HH + h;
        d_Hnew[hidx] = hn;
        d_Hnew_bf[hidx] = __float2bfloat16(hn);
    }
}

// ---------------- projection (BF16 MMA m16n8k16 + cp.async, BK=32) ------------
// Block 128x128, 16 K-iterations, 2 stages. Grid (60 m-groups, 79 n-tiles).
__global__ __launch_bounds__(256) void k_proj(const float* __restrict__ b_out,
                                              float* __restrict__ out) {
    __shared__ __nv_bfloat16 As[2][128][40];   // pitch 40 halves = 80B
    __shared__ __nv_bfloat16 Bs[2][128][40];
    const int yo = blockIdx.x;
    const int t = yo >> 1;
    const int b0 = (yo & 1) * 128;
    if (b0 >= d_cnt[t]) return;
    const int m0g = t * 256 + b0;
    const int n0 = blockIdx.y * 128;
    const int tid = threadIdx.x;

    // loaders: rows lrow, lrow+64; chunk lq covers halves [lq*8, lq*8+8)
    const int lrow = tid >> 2, lq = tid & 3;
    const __nv_bfloat16* aS0 = &d_Hnew_bf[(size_t)(m0g + lrow) * HH + lq * 8];
    const __nv_bfloat16* aS1 = &d_Hnew_bf[(size_t)(m0g + lrow + 64) * HH + lq * 8];
    int nB0 = n0 + lrow, nB1 = n0 + lrow + 64;
    unsigned zB0 = nB0 < VV ? 16u : 0u, zB1 = nB1 < VV ? 16u : 0u;
    const __nv_bfloat16* bS0 = &d_Wout_bf[(size_t)(nB0 < VV ? nB0 : VV - 1) * HH + lq * 8];
    const __nv_bfloat16* bS1 = &d_Wout_bf[(size_t)(nB1 < VV ? nB1 : VV - 1) * HH + lq * 8];
    unsigned dA0 = smem_u32(&As[0][lrow][lq * 8]);
    unsigned dA1 = smem_u32(&As[0][lrow + 64][lq * 8]);
    unsigned dB0 = smem_u32(&Bs[0][lrow][lq * 8]);
    unsigned dB1 = smem_u32(&Bs[0][lrow + 64][lq * 8]);
    const unsigned SSTR = 128 * 40 * 2;        // bytes per stage

    const int lane = tid & 31, wid = tid >> 5;
    const int wm = (wid >> 2) * 64, wn = (wid & 3) * 32;
    const int j = lane >> 3, r = lane & 7;
    unsigned aBase = smem_u32(&As[0][0][0]);
    unsigned bBase = smem_u32(&Bs[0][0][0]);
    unsigned aOff[4], bOff[2];
#pragma unroll
    for (int f = 0; f < 4; f++)
        aOff[f] = aBase + ((wm + f * 16 + (j & 1) * 8 + r) * 40 + (j >> 1) * 8) * 2;
#pragma unroll
    for (int p = 0; p < 2; p++)
        bOff[p] = bBase + ((wn + p * 16 + (j >> 1) * 8 + r) * 40 + (j & 1) * 8) * 2;

    float acc[4][4][4] = {};
    CPA16(dA0, aS0); CPA16(dA1, aS1);
    CPA16Z(dB0, bS0, zB0); CPA16Z(dB1, bS1, zB1);
    CPA_COMMIT();
#pragma unroll 1
    for (int ks = 0; ks < 16; ks++) {
        int st = ks & 1;
        if (ks + 1 < 16) {
            int nst = (ks + 1) & 1;
            int k1 = (ks + 1) * 32;            // halves
            CPA16(dA0 + nst * SSTR, aS0 + k1);
            CPA16(dA1 + nst * SSTR, aS1 + k1);
            CPA16Z(dB0 + nst * SSTR, bS0 + k1, zB0);
            CPA16Z(dB1 + nst * SSTR, bS1 + k1, zB1);
            CPA_COMMIT();
            CPA_WAIT1();
        } else {
            CPA_WAIT0();
        }
        __syncthreads();
#pragma unroll
        for (int s = 0; s < 2; s++) {          // two k16 substeps
            unsigned af[4][4], bf[4][2];
#pragma unroll
            for (int f = 0; f < 4; f++)
                LDM4(af[f][0], af[f][1], af[f][2], af[f][3], aOff[f] + st * SSTR + s * 32);
#pragma unroll
            for (int p = 0; p < 2; p++)
                LDM4(bf[2 * p][0], bf[2 * p][1], bf[2 * p + 1][0], bf[2 * p + 1][1],
                     bOff[p] + st * SSTR + s * 32);
#pragma unroll
            for (int mi = 0; mi < 4; mi++)
#pragma unroll
                for (int ni = 0; ni < 4; ni++)
                    MMA_BF16(acc[mi][ni], af[mi], bf[ni]);
        }
        __syncthreads();
    }
    const int gr = lane >> 2, gc = (lane & 3) * 2;
#pragma unroll
    for (int mi = 0; mi < 4; mi++) {
        int lrw = wm + mi * 16 + gr;
        int b1 = b0 + lrw;
        int b2 = b1 + 8;
#pragma unroll
        for (int ni = 0; ni < 4; ni++) {
            int n = n0 + wn + ni * 8 + gc;
            if (n < VV) {
                float bo0 = b_out[n], bo1 = b_out[n + 1];
                float2 v1 = make_float2(acc[mi][ni][0] + bo0, acc[mi][ni][1] + bo1);
                float2 v2 = make_float2(acc[mi][ni][2] + bo0, acc[mi][ni][3] + bo1);
                *(float2*)&out[((size_t)b1 * MAXLEN + t) * VV + n] = v1;
                *(float2*)&out[((size_t)b2 * MAXLEN + t) * VV + n] = v2;
            }
        }
    }
}

// log_softmax in place; inactive rows (t==30 or b>=cnt[t]) -> zeros
__global__ __launch_bounds__(256) void k_lsm(float* __restrict__ out) {
    __shared__ float sx[VV];
    __shared__ float red[256];
    int rid = blockIdx.x;
    int b = rid / MAXLEN, t = rid - b * MAXLEN;
    float* row = out + (size_t)rid * VV;
    int tid = threadIdx.x;
    bool active = (t < TT) && (b < d_cnt[t]);
    if (!active) {
        for (int i = tid; i < VV; i += 256) row[i] = 0.f;
        return;
    }
    float mx = -1e30f;
    for (int i = tid; i < VV; i += 256) {
        float v = row[i];
        sx[i] = v;
        mx = fmaxf(mx, v);
    }
    red[tid] = mx;
    __syncthreads();
    for (int s = 128; s > 0; s >>= 1) {
        if (tid < s) red[tid] = fmaxf(red[tid], red[tid + s]);
        __syncthreads();
    }
    mx = red[0];
    __syncthreads();
    float sm = 0.f;
    for (int i = tid; i < VV; i += 256) sm += expf(sx[i] - mx);
    red[tid] = sm;
    __syncthreads();
    for (int s = 128; s > 0; s >>= 1) {
        if (tid < s) red[tid] += red[tid + s];
        __syncthreads();
    }
    float lse = mx + logf(red[0]);
    for (int i = tid; i < VV; i += 256) row[i] = sx[i] - lse;
}

// ---------------- launch ------------------------------------------------------
extern "C" void kernel_launch(void* const* d_in, const int* in_sizes, int n_in,
                              void* d_out, int out_size) {
    const float* gimg    = (const float*)d_in[0];
    const int*   w_input = (const int*)  d_in[1];
    const int*   caplen  = (const int*)  d_in[2];
    const float* emb     = (const float*)d_in[3];
    const float* W_ih    = (const float*)d_in[4];
    const float* W_hh    = (const float*)d_in[5];
    const float* b_ih    = (const float*)d_in[6];
    const float* b_hh    = (const float*)d_in[7];
    const float* W_out   = (const float*)d_in[8];
    const float* b_out   = (const float*)d_in[9];
    float* out = (float*)d_out;

    k_zero<<<1024, 256>>>();
    k_conv_wout<<<5000, 256>>>(W_out);
    k_sort<<<1, 256>>>(caplen, w_input, out, (long long)out_size);
    k_gpart<<<dim3(32, 4), 256>>>(gimg, W_ih, b_ih, b_hh);
    k_epart_tc<<<dim3(60, 16), 256>>>(emb, W_ih);
    for (int t = 0; t < TT; t++) {
        k_stepcell_tc<<<dim3(8, 8), 256>>>(W_hh, t);
    }
    k_proj<<<dim3(60, 79), 256>>>(b_out, out);
    k_lsm<<<BB * MAXLEN, 256>>>(out);
}